// round 15
// baseline (speedup 1.0000x reference)
#include <cuda_runtime.h>
#include <cuda_bf16.h>
#include <cuda_fp16.h>
#include <math.h>
#include <stdint.h>

// Problem dims
#define SEQ    512
#define NHEAD  12
#define DHEAD  64
#define CDIM   768
#define BPDIM  32              // B*P = 8*4
#define MTOK   (BPDIM * SEQ)   // 16384 tokens
#define QSCALE 0.125f          // 64^-0.5

// ---------------------------------------------------------------------------
// Device-global scratch (allocation-free per harness rules)
// ---------------------------------------------------------------------------
#define HELEMS ((size_t)BPDIM * NHEAD * SEQ * DHEAD)   // 12.58M

// attention operands: single fp16 (q pre-scaled)
__device__ __half g_qf[HELEMS];
__device__ __half g_kf[HELEMS];
__device__ __half g_vf[HELEMS];

// fp16 operands for the two projection GEMMs
__device__ __half g_xf[(size_t)MTOK * CDIM];
__device__ __half g_of[(size_t)MTOK * CDIM];
__device__ __half g_wqf[(size_t)3 * CDIM * CDIM];
__device__ __half g_wpf[(size_t)CDIM * CDIM];

// ---------------------------------------------------------------------------
// Base-ISA tensor helpers (mma.sync + ldmatrix + cp.async — sm_103 base target)
// ---------------------------------------------------------------------------
__device__ __forceinline__ uint32_t smem_u32(const void* p) {
    uint32_t a;
    asm("{ .reg .u64 t; cvta.to.shared.u64 t, %1; cvt.u32.u64 %0, t; }"
        : "=r"(a) : "l"(p));
    return a;
}

__device__ __forceinline__ void ldmx4(uint32_t* r, uint32_t addr) {
    asm volatile("ldmatrix.sync.aligned.m8n8.x4.shared.b16 {%0,%1,%2,%3}, [%4];"
                 : "=r"(r[0]), "=r"(r[1]), "=r"(r[2]), "=r"(r[3]) : "r"(addr));
}
__device__ __forceinline__ void ldmx4t(uint32_t* r, uint32_t addr) {
    asm volatile("ldmatrix.sync.aligned.m8n8.x4.trans.shared.b16 {%0,%1,%2,%3}, [%4];"
                 : "=r"(r[0]), "=r"(r[1]), "=r"(r[2]), "=r"(r[3]) : "r"(addr));
}

__device__ __forceinline__ void mma_f16(float* c, const uint32_t* a,
                                        uint32_t b0, uint32_t b1) {
    asm volatile(
        "mma.sync.aligned.m16n8k16.row.col.f32.f16.f16.f32 "
        "{%0,%1,%2,%3}, {%4,%5,%6,%7}, {%8,%9}, {%0,%1,%2,%3};"
        : "+f"(c[0]), "+f"(c[1]), "+f"(c[2]), "+f"(c[3])
        : "r"(a[0]), "r"(a[1]), "r"(a[2]), "r"(a[3]), "r"(b0), "r"(b1));
}

__device__ __forceinline__ void cp16(uint32_t dst, const void* src) {
    asm volatile("cp.async.cg.shared.global [%0], [%1], 16;"
                 :: "r"(dst), "l"(src) : "memory");
}
#define CP_COMMIT() asm volatile("cp.async.commit_group;" ::: "memory")
#define CP_WAIT1()  asm volatile("cp.async.wait_group 1;" ::: "memory")
#define CP_WAIT0()  asm volatile("cp.async.wait_group 0;" ::: "memory")

// ---------------------------------------------------------------------------
// Merged fp16 convert kernel (grid-stride): x->g_xf, Wqkv->g_wqf, Wproj->g_wpf
// ---------------------------------------------------------------------------
#define NX4 (MTOK * CDIM / 4)              // 3145728
#define NQ4 (3 * CDIM * CDIM / 4)          // 442368
#define NP4 (CDIM * CDIM / 4)              // 147456
#define NALL4 (NX4 + NQ4 + NP4)
#define CONV_BLOCKS 1184                   // 148 SMs * 8

__global__ void conv_all(const float* __restrict__ x,
                         const float* __restrict__ wq,
                         const float* __restrict__ wp)
{
    const int stride = CONV_BLOCKS * 256;
    for (int i = blockIdx.x * 256 + threadIdx.x; i < NALL4; i += stride) {
        const float* src;
        __half* dst;
        int j;
        if (i < NX4)            { src = x;  dst = g_xf;  j = i; }
        else if (i < NX4 + NQ4) { src = wq; dst = g_wqf; j = i - NX4; }
        else                    { src = wp; dst = g_wpf; j = i - NX4 - NQ4; }
        float4 v = ((const float4*)src)[j];
        ((__half2*)dst)[2 * j]     = __floats2half2_rn(v.x, v.y);
        ((__half2*)dst)[2 * j + 1] = __floats2half2_rn(v.z, v.w);
    }
}

// ---------------------------------------------------------------------------
// Tensor-core GEMM (NT), single-product fp16, fp32 accumulate.
// NEW SHAPE: CTA 128x128 with 512 threads / 16 warps, warp tile 32x32
// (4x4 warp grid). Accumulator = 32 regs -> fits the 64-reg cap at
// __launch_bounds__(512,2) => 1024 thr/SM = 8 warps/SMSP of latency coverage.
// BK=64, 3-stage cp.async (96KB), XOR-swizzled 128B rows.
// MODE 0: A=g_xf, B=g_wqf; epilogue: q (scaled) / k / v single fp16.
// MODE 1: A=g_of, B=g_wpf; +bias -> d_out (fp32).
// ---------------------------------------------------------------------------
#define GT_B    16384
#define GSTG_B  (2 * GT_B)      // 32768
#define GSMEM   (3 * GSTG_B)    // 98304
#define NCHUNK  (CDIM / 64)     // 12
#define GTHREADS 512

template <int MODE>
__global__ __launch_bounds__(GTHREADS, 2)
void gemm_tc(float* __restrict__ Cout, const float* __restrict__ bias)
{
    extern __shared__ char smem[];
    const uint32_t sb = smem_u32(smem);
    const int tid = threadIdx.x;
    const int l   = tid & 31;
    const int warp = tid >> 5;        // 0..15
    const int wm = warp & 3;          // 4 m-groups of 32 rows
    const int wn = warp >> 2;         // 4 n-groups of 32 cols
    const int bn = blockIdx.x, bm = blockIdx.y;
    const int K = CDIM;

    const __half* srcs[2] = {
        ((MODE == 0) ? g_xf : g_of) + (size_t)(bm * 128) * K,
        ((MODE == 0) ? g_wqf : g_wpf) + (size_t)(bn * 128) * K };

    const int lrow  = l & 15;
    const int lhalf = l >> 4;

    float acc[2][4][4];
#pragma unroll
    for (int i = 0; i < 2; i++)
#pragma unroll
        for (int j = 0; j < 4; j++)
#pragma unroll
            for (int q = 0; q < 4; q++) acc[i][j][q] = 0.f;

#define LOAD_CHUNK(c, st)                                                      \
    do {                                                                       \
        _Pragma("unroll")                                                      \
        for (int j = 0; j < 4; j++) {                                          \
            const int i = tid + j * GTHREADS;                                  \
            const int t = i >> 10, r = (i >> 3) & 127, u = i & 7;              \
            const uint32_t dst = sb + (st) * GSTG_B + t * GT_B + r * 128       \
                               + ((u ^ (r & 7)) << 4);                         \
            cp16(dst, srcs[t] + (size_t)r * K + (c) * 64 + u * 8);             \
        }                                                                      \
        CP_COMMIT();                                                           \
    } while (0)

    LOAD_CHUNK(0, 0);
    LOAD_CHUNK(1, 1);

    for (int c = 0; c < NCHUNK; c++) {
        CP_WAIT1();
        __syncthreads();
        if (c + 2 < NCHUNK) {
            LOAD_CHUNK(c + 2, (c + 2) % 3);
        } else {
            CP_COMMIT();
        }

        const uint32_t stg = sb + (c % 3) * GSTG_B;
#pragma unroll
        for (int s = 0; s < 4; s++) {
            const int slot = s * 2 + lhalf;
            uint32_t bf[8];
#pragma unroll
            for (int np = 0; np < 2; np++) {
                const int R = wn * 32 + np * 16 + lrow;
                const uint32_t off = R * 128 + ((slot ^ (R & 7)) << 4);
                ldmx4(&bf[np * 4], stg + GT_B + off);
            }
#pragma unroll
            for (int mt = 0; mt < 2; mt++) {
                const int R = wm * 32 + mt * 16 + lrow;
                const uint32_t off = R * 128 + ((slot ^ (R & 7)) << 4);
                uint32_t af[4];
                ldmx4(af, stg + off);
#pragma unroll
                for (int nt = 0; nt < 4; nt++) {
                    const int np = nt >> 1, q = nt & 1;
                    mma_f16(acc[mt][nt], af, bf[np * 4 + q], bf[np * 4 + q + 2]);
                }
            }
        }
    }
#undef LOAD_CHUNK

#pragma unroll
    for (int mt = 0; mt < 2; mt++) {
#pragma unroll
        for (int nt = 0; nt < 4; nt++) {
            const int m0 = bm * 128 + wm * 32 + mt * 16 + (l >> 2);
            const int d  = bn * 128 + wn * 32 + nt * 8 + 2 * (l & 3);
#pragma unroll
            for (int half = 0; half < 2; half++) {
                const int m = m0 + half * 8;
                const float v0 = acc[mt][nt][half * 2 + 0];
                const float v1 = acc[mt][nt][half * 2 + 1];
                if (MODE == 0) {
                    const int bp = m >> 9;
                    const int n  = m & (SEQ - 1);
                    const int ss  = d / CDIM;
                    const int rem = d - ss * CDIM;
                    const int h   = rem >> 6;
                    const int hd  = rem & 63;
                    const size_t base = ((size_t)(bp * NHEAD + h) * SEQ + n) * DHEAD + hd;
                    const float sc = (ss == 0) ? QSCALE : 1.0f;
                    __half* dst = (ss == 0) ? g_qf : (ss == 1) ? g_kf : g_vf;
                    *(__half2*)(dst + base) = __floats2half2_rn(v0 * sc, v1 * sc);
                } else {
                    float2 bv = *(const float2*)(bias + d);
                    *(float2*)(Cout + (size_t)m * CDIM + d) =
                        make_float2(v0 + bv.x, v1 + bv.y);
                }
            }
        }
    }
}

// ---------------------------------------------------------------------------
// Flash attention v3 (unchanged): 128 queries/block, 8 warps each owning 16
// full rows; single-product fp16 QK^T and PV, fp32 accumulate; row max/sum
// within a lane quad; O normalized in registers -> g_of.
// SMEM: Q 18KB + KV 2x18KB = 54KB -> 2 CTA/SM.
// ---------------------------------------------------------------------------
#define AT_STRIDE 144
#define Q_TILE    (128 * AT_STRIDE)         // 18432
#define KV_TILE   (64 * AT_STRIDE)          // 9216
#define ASM_KV    Q_TILE                    // 18432
#define ASM_STG   (2 * KV_TILE)             // 18432 per stage (K, V)
#define ATTN_SMEM (ASM_KV + 2 * ASM_STG)    // 55296

__global__ __launch_bounds__(256, 2)
void attn_flash()
{
    extern __shared__ char sm[];
    const uint32_t sb = smem_u32(sm);

    const int tid = threadIdx.x, l = tid & 31, w = tid >> 5;
    const int bph = blockIdx.x, qt = blockIdx.y;   // qt in 0..3 (128-query tiles)
    const size_t hoff = (size_t)bph * SEQ * DHEAD;
    const __half* qf = g_qf + hoff + (size_t)qt * 128 * DHEAD;
    const __half* asrc[2] = { g_kf + hoff, g_vf + hoff };

    const int lrow = l & 15;
    const int lcolb = (l >> 4) << 4;
    const int r0 = w * 16 + (l >> 2);   // warp-owned query row (and +8)

#define ALOAD(c, st)                                                           \
    do {                                                                       \
        _Pragma("unroll")                                                      \
        for (int j = 0; j < 4; j++) {                                          \
            const int i = tid + j * 256;                                       \
            const int t = i >> 9, r = (i >> 3) & 63, u = i & 7;                \
            cp16(sb + ASM_KV + (st) * ASM_STG + t * KV_TILE + r * AT_STRIDE    \
                     + u * 16,                                                 \
                 asrc[t] + (size_t)(c) * 64 * 64 + r * 64 + u * 8);            \
        }                                                                      \
        CP_COMMIT();                                                           \
    } while (0)

    ALOAD(0, 0);

    // Q tile: 128 rows x 64 halves, one-time plain stores
    for (int i = tid; i < 1024; i += 256) {
        const int r = i >> 3, u = i & 7;
        *(uint4*)(sm + r * AT_STRIDE + u * 16) = *(const uint4*)(qf + r * 64 + u * 8);
    }

    float accO[8][4];
#pragma unroll
    for (int i = 0; i < 8; i++)
#pragma unroll
        for (int q = 0; q < 4; q++) accO[i][q] = 0.f;
    float mrun0 = -1e30f, mrun1 = -1e30f;
    float lsum0 = 0.f, lsum1 = 0.f;

    for (int kc = 0; kc < 8; kc++) {
        if (kc < 7) { ALOAD(kc + 1, (kc + 1) & 1); CP_WAIT1(); }
        else        { CP_WAIT0(); }
        __syncthreads();

        const uint32_t stg = sb + ASM_KV + (kc & 1) * ASM_STG;

        // ---- QK^T: 16 queries x 64 keys, single product ----
        float accS[8][4];
#pragma unroll
        for (int i = 0; i < 8; i++)
#pragma unroll
            for (int q = 0; q < 4; q++) accS[i][q] = 0.f;
#pragma unroll
        for (int ks = 0; ks < 4; ks++) {
            uint32_t qfr[4];
            const uint32_t qro = (w * 16 + lrow) * AT_STRIDE + ks * 32 + lcolb;
            ldmx4(qfr, sb + qro);
            uint32_t kb[16];
#pragma unroll
            for (int np = 0; np < 4; np++) {
                const uint32_t off = (np * 16 + lrow) * AT_STRIDE + ks * 32 + lcolb;
                ldmx4(&kb[np * 4], stg + off);
            }
#pragma unroll
            for (int nt = 0; nt < 8; nt++) {
                const int np = nt >> 1, q = nt & 1;
                mma_f16(accS[nt], qfr, kb[np * 4 + q], kb[np * 4 + q + 2]);
            }
        }

        // ---- online softmax: row max within lane quad ----
        float ml0 = -1e30f, ml1 = -1e30f;
#pragma unroll
        for (int nt = 0; nt < 8; nt++) {
            ml0 = fmaxf(ml0, fmaxf(accS[nt][0], accS[nt][1]));
            ml1 = fmaxf(ml1, fmaxf(accS[nt][2], accS[nt][3]));
        }
        ml0 = fmaxf(ml0, __shfl_xor_sync(0xffffffffu, ml0, 1));
        ml0 = fmaxf(ml0, __shfl_xor_sync(0xffffffffu, ml0, 2));
        ml1 = fmaxf(ml1, __shfl_xor_sync(0xffffffffu, ml1, 1));
        ml1 = fmaxf(ml1, __shfl_xor_sync(0xffffffffu, ml1, 2));
        const float mn0 = fmaxf(mrun0, ml0), mn1 = fmaxf(mrun1, ml1);
        const float sc0 = __expf(mrun0 - mn0), sc1 = __expf(mrun1 - mn1);
        mrun0 = mn0; mrun1 = mn1;
        lsum0 *= sc0; lsum1 *= sc1;
#pragma unroll
        for (int nt = 0; nt < 8; nt++) {
            accO[nt][0] *= sc0; accO[nt][1] *= sc0;
            accO[nt][2] *= sc1; accO[nt][3] *= sc1;
        }

        // ---- P=exp -> fp16 A-frags -> PV, per 16-key group ----
        float ps0 = 0.f, ps1 = 0.f;
#pragma unroll
        for (int kb2 = 0; kb2 < 4; kb2++) {
            const float p00 = __expf(accS[2 * kb2][0] - mn0);
            const float p01 = __expf(accS[2 * kb2][1] - mn0);
            const float p10 = __expf(accS[2 * kb2][2] - mn1);
            const float p11 = __expf(accS[2 * kb2][3] - mn1);
            const float p20 = __expf(accS[2 * kb2 + 1][0] - mn0);
            const float p21 = __expf(accS[2 * kb2 + 1][1] - mn0);
            const float p30 = __expf(accS[2 * kb2 + 1][2] - mn1);
            const float p31 = __expf(accS[2 * kb2 + 1][3] - mn1);
            ps0 += p00 + p01 + p20 + p21;
            ps1 += p10 + p11 + p30 + p31;
            uint32_t Pf[4];
            __half2 t0 = __floats2half2_rn(p00, p01); Pf[0] = *(uint32_t*)&t0;
            __half2 t1 = __floats2half2_rn(p10, p11); Pf[1] = *(uint32_t*)&t1;
            __half2 t2 = __floats2half2_rn(p20, p21); Pf[2] = *(uint32_t*)&t2;
            __half2 t3 = __floats2half2_rn(p30, p31); Pf[3] = *(uint32_t*)&t3;
#pragma unroll
            for (int np = 0; np < 4; np++) {
                uint32_t vb[4];
                const uint32_t ad =
                    (kb2 * 16 + (l & 7) + (((l >> 3) & 1) << 3)) * AT_STRIDE
                    + (np * 16 + ((l >> 4) << 3)) * 2;
                ldmx4t(vb, stg + KV_TILE + ad);
#pragma unroll
                for (int q = 0; q < 2; q++)
                    mma_f16(accO[np * 2 + q], Pf, vb[2 * q], vb[2 * q + 1]);
            }
        }
        ps0 += __shfl_xor_sync(0xffffffffu, ps0, 1);
        ps0 += __shfl_xor_sync(0xffffffffu, ps0, 2);
        ps1 += __shfl_xor_sync(0xffffffffu, ps1, 1);
        ps1 += __shfl_xor_sync(0xffffffffu, ps1, 2);
        lsum0 += ps0; lsum1 += ps1;

        __syncthreads();   // stage reuse fence
    }
#undef ALOAD

    // ---- epilogue: normalize in registers, store fp16 direct to global ----
    const int h  = bph % NHEAD;
    const int bp = bph / NHEAD;
    const float inv0 = 1.0f / lsum0;
    const float inv1 = 1.0f / lsum1;
    const size_t row0 = ((size_t)bp * SEQ + qt * 128 + r0) * CDIM + h * DHEAD;
    const size_t row1 = row0 + (size_t)8 * CDIM;
#pragma unroll
    for (int nt = 0; nt < 8; nt++) {
        const int col = nt * 8 + 2 * (l & 3);
        *(__half2*)(g_of + row0 + col) =
            __floats2half2_rn(accO[nt][0] * inv0, accO[nt][1] * inv0);
        *(__half2*)(g_of + row1 + col) =
            __floats2half2_rn(accO[nt][2] * inv1, accO[nt][3] * inv1);
    }
}

// ---------------------------------------------------------------------------
extern "C" void kernel_launch(void* const* d_in, const int* in_sizes, int n_in,
                              void* d_out, int out_size)
{
    const float* x     = (const float*)d_in[0];  // (8,4,512,768)
    const float* Wqkv  = (const float*)d_in[1];  // (2304,768)
    const float* Wproj = (const float*)d_in[2];  // (768,768)
    const float* bproj = (const float*)d_in[3];  // (768,)
    float* out = (float*)d_out;

    cudaFuncSetAttribute(gemm_tc<0>, cudaFuncAttributeMaxDynamicSharedMemorySize, GSMEM);
    cudaFuncSetAttribute(gemm_tc<1>, cudaFuncAttributeMaxDynamicSharedMemorySize, GSMEM);
    cudaFuncSetAttribute(attn_flash, cudaFuncAttributeMaxDynamicSharedMemorySize, ATTN_SMEM);

    // All three fp32->fp16 conversions, grid-stride
    conv_all<<<CONV_BLOCKS, 256>>>(x, Wqkv, Wproj);

    // QKV projection (fp16); epilogue: q (scaled) / k / v single fp16
    gemm_tc<0><<<dim3(3 * CDIM / 128, MTOK / 128), GTHREADS, GSMEM>>>(nullptr, nullptr);

    // Flash attention v3: single-product fp16, 128 queries/block
    attn_flash<<<dim3(BPDIM * NHEAD, SEQ / 128), 256, ATTN_SMEM>>>();

    // Output projection (fp16) + bias -> d_out
    gemm_tc<1><<<dim3(CDIM / 128, MTOK / 128), GTHREADS, GSMEM>>>(out, bproj);
}

// round 16
// speedup vs baseline: 1.0629x; 1.0629x over previous
#include <cuda_runtime.h>
#include <cuda_bf16.h>
#include <cuda_fp16.h>
#include <math.h>
#include <stdint.h>

// Problem dims
#define SEQ    512
#define NHEAD  12
#define DHEAD  64
#define CDIM   768
#define BPDIM  32              // B*P = 8*4
#define MTOK   (BPDIM * SEQ)   // 16384 tokens
#define QSCALE 0.125f          // 64^-0.5

// ---------------------------------------------------------------------------
// Device-global scratch (allocation-free per harness rules)
// ---------------------------------------------------------------------------
#define HELEMS ((size_t)BPDIM * NHEAD * SEQ * DHEAD)   // 12.58M

// attention operands: single fp16 (q pre-scaled)
__device__ __half g_qf[HELEMS];
__device__ __half g_kf[HELEMS];
__device__ __half g_vf[HELEMS];

// fp16 operands for the two projection GEMMs
__device__ __half g_xf[(size_t)MTOK * CDIM];
__device__ __half g_of[(size_t)MTOK * CDIM];
__device__ __half g_wqf[(size_t)3 * CDIM * CDIM];
__device__ __half g_wpf[(size_t)CDIM * CDIM];

// ---------------------------------------------------------------------------
// Base-ISA tensor helpers (mma.sync + ldmatrix + cp.async — sm_103 base target)
// ---------------------------------------------------------------------------
__device__ __forceinline__ uint32_t smem_u32(const void* p) {
    uint32_t a;
    asm("{ .reg .u64 t; cvta.to.shared.u64 t, %1; cvt.u32.u64 %0, t; }"
        : "=r"(a) : "l"(p));
    return a;
}

__device__ __forceinline__ void ldmx4(uint32_t* r, uint32_t addr) {
    asm volatile("ldmatrix.sync.aligned.m8n8.x4.shared.b16 {%0,%1,%2,%3}, [%4];"
                 : "=r"(r[0]), "=r"(r[1]), "=r"(r[2]), "=r"(r[3]) : "r"(addr));
}
__device__ __forceinline__ void ldmx4t(uint32_t* r, uint32_t addr) {
    asm volatile("ldmatrix.sync.aligned.m8n8.x4.trans.shared.b16 {%0,%1,%2,%3}, [%4];"
                 : "=r"(r[0]), "=r"(r[1]), "=r"(r[2]), "=r"(r[3]) : "r"(addr));
}

__device__ __forceinline__ void mma_f16(float* c, const uint32_t* a,
                                        uint32_t b0, uint32_t b1) {
    asm volatile(
        "mma.sync.aligned.m16n8k16.row.col.f32.f16.f16.f32 "
        "{%0,%1,%2,%3}, {%4,%5,%6,%7}, {%8,%9}, {%0,%1,%2,%3};"
        : "+f"(c[0]), "+f"(c[1]), "+f"(c[2]), "+f"(c[3])
        : "r"(a[0]), "r"(a[1]), "r"(a[2]), "r"(a[3]), "r"(b0), "r"(b1));
}

__device__ __forceinline__ void cp16(uint32_t dst, const void* src) {
    asm volatile("cp.async.cg.shared.global [%0], [%1], 16;"
                 :: "r"(dst), "l"(src) : "memory");
}
#define CP_COMMIT() asm volatile("cp.async.commit_group;" ::: "memory")
#define CP_WAIT1()  asm volatile("cp.async.wait_group 1;" ::: "memory")
#define CP_WAIT0()  asm volatile("cp.async.wait_group 0;" ::: "memory")

// ---------------------------------------------------------------------------
// Merged fp16 convert kernel (grid-stride): x->g_xf, Wqkv->g_wqf, Wproj->g_wpf
// ---------------------------------------------------------------------------
#define NX4 (MTOK * CDIM / 4)              // 3145728
#define NQ4 (3 * CDIM * CDIM / 4)          // 442368
#define NP4 (CDIM * CDIM / 4)              // 147456
#define NALL4 (NX4 + NQ4 + NP4)
#define CONV_BLOCKS 1184                   // 148 SMs * 8

__global__ void conv_all(const float* __restrict__ x,
                         const float* __restrict__ wq,
                         const float* __restrict__ wp)
{
    const int stride = CONV_BLOCKS * 256;
    for (int i = blockIdx.x * 256 + threadIdx.x; i < NALL4; i += stride) {
        const float* src;
        __half* dst;
        int j;
        if (i < NX4)            { src = x;  dst = g_xf;  j = i; }
        else if (i < NX4 + NQ4) { src = wq; dst = g_wqf; j = i - NX4; }
        else                    { src = wp; dst = g_wpf; j = i - NX4 - NQ4; }
        float4 v = ((const float4*)src)[j];
        ((__half2*)dst)[2 * j]     = __floats2half2_rn(v.x, v.y);
        ((__half2*)dst)[2 * j + 1] = __floats2half2_rn(v.z, v.w);
    }
}

// ---------------------------------------------------------------------------
// Tensor-core GEMM (NT), single-product fp16, fp32 accumulate.
// Round-14 measured optimum: CTA 128x128, 256 thr / 8 warps, warp tile 64x32,
// BK=64, 3-stage cp.async, XOR-swizzled 128B rows, __launch_bounds__(256,2),
// per-warp k16-step phase rotation.
// MODE 0: A=g_xf, B=g_wqf; epilogue: q (scaled) / k / v single fp16.
// MODE 1: A=g_of, B=g_wpf; +bias -> d_out (fp32).
// ---------------------------------------------------------------------------
#define GT_B    16384
#define GSTG_B  (2 * GT_B)      // 32768
#define GSMEM   (3 * GSTG_B)    // 98304
#define NCHUNK  (CDIM / 64)     // 12

template <int MODE>
__global__ __launch_bounds__(256, 2)
void gemm_tc(float* __restrict__ Cout, const float* __restrict__ bias)
{
    extern __shared__ char smem[];
    const uint32_t sb = smem_u32(smem);
    const int tid = threadIdx.x;
    const int l   = tid & 31;
    const int warp = tid >> 5;
    const int wm = warp & 1;
    const int wn = warp >> 1;
    const int bn = blockIdx.x, bm = blockIdx.y;
    const int K = CDIM;

    // per-warp k16-step phase offset (SMSP pair gets offsets 2 apart)
    const int off = (warp + 2 * (warp >> 2)) & 3;

    const __half* srcs[2] = {
        ((MODE == 0) ? g_xf : g_of) + (size_t)(bm * 128) * K,
        ((MODE == 0) ? g_wqf : g_wpf) + (size_t)(bn * 128) * K };

    const int lrow  = l & 15;
    const int lhalf = l >> 4;

    float acc[4][4][4];
#pragma unroll
    for (int i = 0; i < 4; i++)
#pragma unroll
        for (int j = 0; j < 4; j++)
#pragma unroll
            for (int q = 0; q < 4; q++) acc[i][j][q] = 0.f;

#define LOAD_CHUNK(c, st)                                                      \
    do {                                                                       \
        _Pragma("unroll")                                                      \
        for (int j = 0; j < 8; j++) {                                          \
            const int i = tid + j * 256;                                       \
            const int t = i >> 10, r = (i >> 3) & 127, u = i & 7;              \
            const uint32_t dst = sb + (st) * GSTG_B + t * GT_B + r * 128       \
                               + ((u ^ (r & 7)) << 4);                         \
            cp16(dst, srcs[t] + (size_t)r * K + (c) * 64 + u * 8);             \
        }                                                                      \
        CP_COMMIT();                                                           \
    } while (0)

#define LOADB(s, dst)                                                          \
    do {                                                                       \
        const int slot_ = (s) * 2 + lhalf;                                     \
        _Pragma("unroll")                                                      \
        for (int np = 0; np < 2; np++) {                                       \
            const int R = wn * 32 + np * 16 + lrow;                            \
            ldmx4(&(dst)[np * 4],                                              \
                  stg + GT_B + R * 128 + ((slot_ ^ (R & 7)) << 4));            \
        }                                                                      \
    } while (0)
#define LOADA(s, mt, dst)                                                      \
    do {                                                                       \
        const int slot_ = (s) * 2 + lhalf;                                     \
        const int R = wm * 64 + (mt) * 16 + lrow;                              \
        ldmx4(dst, stg + R * 128 + ((slot_ ^ (R & 7)) << 4));                  \
    } while (0)

    LOAD_CHUNK(0, 0);
    LOAD_CHUNK(1, 1);

    for (int c = 0; c < NCHUNK; c++) {
        CP_WAIT1();
        __syncthreads();
        if (c + 2 < NCHUNK) {
            LOAD_CHUNK(c + 2, (c + 2) % 3);
        } else {
            CP_COMMIT();
        }

        const uint32_t stg = sb + (c % 3) * GSTG_B;

        uint32_t bf[2][8], af[2][4];
        LOADB(off, bf[0]);
#pragma unroll
        for (int i = 0; i < 4; i++) {
            const int cs = i & 1;
            const int sp = (i + off) & 3;          // phase-rotated k16 step
            if (i < 3) LOADB((i + 1 + off) & 3, bf[cs ^ 1]);
            LOADA(sp, 0, af[0]);
#pragma unroll
            for (int mt = 0; mt < 4; mt++) {
                if (mt < 3) LOADA(sp, mt + 1, af[(mt + 1) & 1]);
#pragma unroll
                for (int nt = 0; nt < 4; nt++) {
                    const int np = nt >> 1, q = nt & 1;
                    mma_f16(acc[mt][nt], af[mt & 1],
                            bf[cs][np * 4 + q], bf[cs][np * 4 + q + 2]);
                }
            }
        }
    }
#undef LOAD_CHUNK
#undef LOADB
#undef LOADA

#pragma unroll
    for (int mt = 0; mt < 4; mt++) {
#pragma unroll
        for (int nt = 0; nt < 4; nt++) {
            const int m0 = bm * 128 + wm * 64 + mt * 16 + (l >> 2);
            const int d  = bn * 128 + wn * 32 + nt * 8 + 2 * (l & 3);
#pragma unroll
            for (int half = 0; half < 2; half++) {
                const int m = m0 + half * 8;
                const float v0 = acc[mt][nt][half * 2 + 0];
                const float v1 = acc[mt][nt][half * 2 + 1];
                if (MODE == 0) {
                    const int bp = m >> 9;
                    const int n  = m & (SEQ - 1);
                    const int ss  = d / CDIM;
                    const int rem = d - ss * CDIM;
                    const int h   = rem >> 6;
                    const int hd  = rem & 63;
                    const size_t base = ((size_t)(bp * NHEAD + h) * SEQ + n) * DHEAD + hd;
                    const float sc = (ss == 0) ? QSCALE : 1.0f;
                    __half* dst = (ss == 0) ? g_qf : (ss == 1) ? g_kf : g_vf;
                    *(__half2*)(dst + base) = __floats2half2_rn(v0 * sc, v1 * sc);
                } else {
                    float2 bv = *(const float2*)(bias + d);
                    *(float2*)(Cout + (size_t)m * CDIM + d) =
                        make_float2(v0 + bv.x, v1 + bv.y);
                }
            }
        }
    }
}

// ---------------------------------------------------------------------------
// Flash attention v4: 128 queries/block, 8 warps each owning 16 full rows;
// single-product fp16 QK^T and PV, fp32 accumulate; row max/sum within a
// lane quad; O normalized in registers -> g_of.
// NEW: 3-stage KV cp.async pipeline (prefetch distance 2) — the wait at chunk
// k targets a group issued two chunks ago, fully covered by compute.
// SMEM: Q 18KB + KV 3x18KB = 72KB -> 2 CTA/SM.
// ---------------------------------------------------------------------------
#define AT_STRIDE 144
#define Q_TILE    (128 * AT_STRIDE)         // 18432
#define KV_TILE   (64 * AT_STRIDE)          // 9216
#define ASM_KV    Q_TILE                    // 18432
#define ASM_STG   (2 * KV_TILE)             // 18432 per stage (K, V)
#define ATTN_SMEM (ASM_KV + 3 * ASM_STG)    // 73728

__global__ __launch_bounds__(256, 2)
void attn_flash()
{
    extern __shared__ char sm[];
    const uint32_t sb = smem_u32(sm);

    const int tid = threadIdx.x, l = tid & 31, w = tid >> 5;
    const int bph = blockIdx.x, qt = blockIdx.y;   // qt in 0..3 (128-query tiles)
    const size_t hoff = (size_t)bph * SEQ * DHEAD;
    const __half* qf = g_qf + hoff + (size_t)qt * 128 * DHEAD;
    const __half* asrc[2] = { g_kf + hoff, g_vf + hoff };

    const int lrow = l & 15;
    const int lcolb = (l >> 4) << 4;
    const int r0 = w * 16 + (l >> 2);   // warp-owned query row (and +8)

#define ALOAD(c, st)                                                           \
    do {                                                                       \
        _Pragma("unroll")                                                      \
        for (int j = 0; j < 4; j++) {                                          \
            const int i = tid + j * 256;                                       \
            const int t = i >> 9, r = (i >> 3) & 63, u = i & 7;                \
            cp16(sb + ASM_KV + (st) * ASM_STG + t * KV_TILE + r * AT_STRIDE    \
                     + u * 16,                                                 \
                 asrc[t] + (size_t)(c) * 64 * 64 + r * 64 + u * 8);            \
        }                                                                      \
        CP_COMMIT();                                                           \
    } while (0)

    ALOAD(0, 0);
    ALOAD(1, 1);

    // Q tile: 128 rows x 64 halves, one-time plain stores
    for (int i = tid; i < 1024; i += 256) {
        const int r = i >> 3, u = i & 7;
        *(uint4*)(sm + r * AT_STRIDE + u * 16) = *(const uint4*)(qf + r * 64 + u * 8);
    }

    float accO[8][4];
#pragma unroll
    for (int i = 0; i < 8; i++)
#pragma unroll
        for (int q = 0; q < 4; q++) accO[i][q] = 0.f;
    float mrun0 = -1e30f, mrun1 = -1e30f;
    float lsum0 = 0.f, lsum1 = 0.f;

    for (int kc = 0; kc < 8; kc++) {
        CP_WAIT1();
        __syncthreads();   // chunk kc visible; stage (kc+2)%3 fully consumed
        if (kc + 2 < 8) {
            ALOAD(kc + 2, (kc + 2) % 3);
        } else {
            CP_COMMIT();
        }

        const uint32_t stg = sb + ASM_KV + (kc % 3) * ASM_STG;

        // ---- QK^T: 16 queries x 64 keys, single product ----
        float accS[8][4];
#pragma unroll
        for (int i = 0; i < 8; i++)
#pragma unroll
            for (int q = 0; q < 4; q++) accS[i][q] = 0.f;
#pragma unroll
        for (int ks = 0; ks < 4; ks++) {
            uint32_t qfr[4];
            const uint32_t qro = (w * 16 + lrow) * AT_STRIDE + ks * 32 + lcolb;
            ldmx4(qfr, sb + qro);
            uint32_t kb[16];
#pragma unroll
            for (int np = 0; np < 4; np++) {
                const uint32_t off = (np * 16 + lrow) * AT_STRIDE + ks * 32 + lcolb;
                ldmx4(&kb[np * 4], stg + off);
            }
#pragma unroll
            for (int nt = 0; nt < 8; nt++) {
                const int np = nt >> 1, q = nt & 1;
                mma_f16(accS[nt], qfr, kb[np * 4 + q], kb[np * 4 + q + 2]);
            }
        }

        // ---- online softmax: row max within lane quad ----
        float ml0 = -1e30f, ml1 = -1e30f;
#pragma unroll
        for (int nt = 0; nt < 8; nt++) {
            ml0 = fmaxf(ml0, fmaxf(accS[nt][0], accS[nt][1]));
            ml1 = fmaxf(ml1, fmaxf(accS[nt][2], accS[nt][3]));
        }
        ml0 = fmaxf(ml0, __shfl_xor_sync(0xffffffffu, ml0, 1));
        ml0 = fmaxf(ml0, __shfl_xor_sync(0xffffffffu, ml0, 2));
        ml1 = fmaxf(ml1, __shfl_xor_sync(0xffffffffu, ml1, 1));
        ml1 = fmaxf(ml1, __shfl_xor_sync(0xffffffffu, ml1, 2));
        const float mn0 = fmaxf(mrun0, ml0), mn1 = fmaxf(mrun1, ml1);
        const float sc0 = __expf(mrun0 - mn0), sc1 = __expf(mrun1 - mn1);
        mrun0 = mn0; mrun1 = mn1;
        lsum0 *= sc0; lsum1 *= sc1;
#pragma unroll
        for (int nt = 0; nt < 8; nt++) {
            accO[nt][0] *= sc0; accO[nt][1] *= sc0;
            accO[nt][2] *= sc1; accO[nt][3] *= sc1;
        }

        // ---- P=exp -> fp16 A-frags -> PV, per 16-key group ----
        float ps0 = 0.f, ps1 = 0.f;
#pragma unroll
        for (int kb2 = 0; kb2 < 4; kb2++) {
            const float p00 = __expf(accS[2 * kb2][0] - mn0);
            const float p01 = __expf(accS[2 * kb2][1] - mn0);
            const float p10 = __expf(accS[2 * kb2][2] - mn1);
            const float p11 = __expf(accS[2 * kb2][3] - mn1);
            const float p20 = __expf(accS[2 * kb2 + 1][0] - mn0);
            const float p21 = __expf(accS[2 * kb2 + 1][1] - mn0);
            const float p30 = __expf(accS[2 * kb2 + 1][2] - mn1);
            const float p31 = __expf(accS[2 * kb2 + 1][3] - mn1);
            ps0 += p00 + p01 + p20 + p21;
            ps1 += p10 + p11 + p30 + p31;
            uint32_t Pf[4];
            __half2 t0 = __floats2half2_rn(p00, p01); Pf[0] = *(uint32_t*)&t0;
            __half2 t1 = __floats2half2_rn(p10, p11); Pf[1] = *(uint32_t*)&t1;
            __half2 t2 = __floats2half2_rn(p20, p21); Pf[2] = *(uint32_t*)&t2;
            __half2 t3 = __floats2half2_rn(p30, p31); Pf[3] = *(uint32_t*)&t3;
#pragma unroll
            for (int np = 0; np < 4; np++) {
                uint32_t vb[4];
                const uint32_t ad =
                    (kb2 * 16 + (l & 7) + (((l >> 3) & 1) << 3)) * AT_STRIDE
                    + (np * 16 + ((l >> 4) << 3)) * 2;
                ldmx4t(vb, stg + KV_TILE + ad);
#pragma unroll
                for (int q = 0; q < 2; q++)
                    mma_f16(accO[np * 2 + q], Pf, vb[2 * q], vb[2 * q + 1]);
            }
        }
        ps0 += __shfl_xor_sync(0xffffffffu, ps0, 1);
        ps0 += __shfl_xor_sync(0xffffffffu, ps0, 2);
        ps1 += __shfl_xor_sync(0xffffffffu, ps1, 1);
        ps1 += __shfl_xor_sync(0xffffffffu, ps1, 2);
        lsum0 += ps0; lsum1 += ps1;
    }
#undef ALOAD

    // ---- epilogue: normalize in registers, store fp16 direct to global ----
    const int h  = bph % NHEAD;
    const int bp = bph / NHEAD;
    const float inv0 = 1.0f / lsum0;
    const float inv1 = 1.0f / lsum1;
    const size_t row0 = ((size_t)bp * SEQ + qt * 128 + r0) * CDIM + h * DHEAD;
    const size_t row1 = row0 + (size_t)8 * CDIM;
#pragma unroll
    for (int nt = 0; nt < 8; nt++) {
        const int col = nt * 8 + 2 * (l & 3);
        *(__half2*)(g_of + row0 + col) =
            __floats2half2_rn(accO[nt][0] * inv0, accO[nt][1] * inv0);
        *(__half2*)(g_of + row1 + col) =
            __floats2half2_rn(accO[nt][2] * inv1, accO[nt][3] * inv1);
    }
}

// ---------------------------------------------------------------------------
extern "C" void kernel_launch(void* const* d_in, const int* in_sizes, int n_in,
                              void* d_out, int out_size)
{
    const float* x     = (const float*)d_in[0];  // (8,4,512,768)
    const float* Wqkv  = (const float*)d_in[1];  // (2304,768)
    const float* Wproj = (const float*)d_in[2];  // (768,768)
    const float* bproj = (const float*)d_in[3];  // (768,)
    float* out = (float*)d_out;

    cudaFuncSetAttribute(gemm_tc<0>, cudaFuncAttributeMaxDynamicSharedMemorySize, GSMEM);
    cudaFuncSetAttribute(gemm_tc<1>, cudaFuncAttributeMaxDynamicSharedMemorySize, GSMEM);
    cudaFuncSetAttribute(attn_flash, cudaFuncAttributeMaxDynamicSharedMemorySize, ATTN_SMEM);

    // All three fp32->fp16 conversions, grid-stride
    conv_all<<<CONV_BLOCKS, 256>>>(x, Wqkv, Wproj);

    // QKV projection (fp16); epilogue: q (scaled) / k / v single fp16
    gemm_tc<0><<<dim3(3 * CDIM / 128, MTOK / 128), 256, GSMEM>>>(nullptr, nullptr);

    // Flash attention v4: 3-stage KV pipeline, single-product fp16
    attn_flash<<<dim3(BPDIM * NHEAD, SEQ / 128), 256, ATTN_SMEM>>>();

    // Output projection (fp16) + bias -> d_out
    gemm_tc<1><<<dim3(CDIM / 128, MTOK / 128), 256, GSMEM>>>(out, bproj);
}